// round 3
// baseline (speedup 1.0000x reference)
#include <cuda_runtime.h>
#include <math.h>
#include <stdint.h>

#define BB 512
#define TT 64
#define NLL 32
#define LATD 64
#define HIDD 128
#define DIN 65
#define G3 384
#define TMAXV 2000
#define QPADV 2000
#define MAXG 160
#define SCALE_F 365.0f

// ------------------------ device scratch (static, no allocs) ----------------
__device__ float  g_GI[BB*TT*G3];
__device__ float  g_h[BB*HIDD];
__device__ float  g_z0[BB*LATD];
__device__ int    g_pres[TMAXV];
__device__ int    g_rank[TMAXV];
__device__ float  g_qt[QPADV];
__device__ float  g_grid[MAXG];
__device__ int    g_niters;
__device__ int    g_maskmode;
__device__ double g_sse, g_nobs, g_kl;
__device__ float  g_ys[(size_t)MAXG*BB*LATD];

// ------------------------ helpers -------------------------------------------
__device__ __forceinline__ float fsigm(float x){ return 1.0f/(1.0f+expf(-x)); }

__device__ __forceinline__ float mread(const void* m, size_t idx, int mode){
    if(mode==0) return ((const unsigned char*)m)[idx] ? 1.0f : 0.0f;
    if(mode==1) return ((const int*)m)[idx]           ? 1.0f : 0.0f;
    return ((const float*)m)[idx] != 0.0f ? 1.0f : 0.0f;
}

// ------------------------ k0: zero state ------------------------------------
__global__ void k_zero(){
    int i = blockIdx.x*blockDim.x + threadIdx.x;
    if(i < TMAXV) g_pres[i] = 0;
    if(i == 0){ g_sse = 0.0; g_nobs = 0.0; g_kl = 0.0; }
}

// ------------------------ k1: detect mask dtype -----------------------------
__global__ void k_detect(const void* m){
    __shared__ int flags[3]; // notF32, hasOne, isU8
    int tid = threadIdx.x;
    if(tid < 3) flags[tid] = 0;
    __syncthreads();
    const unsigned int* w = (const unsigned int*)m;
    int notf = 0, one = 0;
    for(int i = tid; i < 1024; i += 256){
        unsigned v = w[i];
        if(v == 0x3f800000u) one = 1; else if(v != 0u) notf = 1;
    }
    const unsigned char* c = (const unsigned char*)m;
    int u8 = 0;
    for(int i = tid; i < 4096; i += 256){ if((i & 3) && c[i]) u8 = 1; }
    if(notf) atomicOr(&flags[0], 1);
    if(one)  atomicOr(&flags[1], 1);
    if(u8)   atomicOr(&flags[2], 1);
    __syncthreads();
    if(tid == 0){
        if(!flags[0] && flags[1]) g_maskmode = 2;
        else g_maskmode = flags[2] ? 0 : 1;
    }
}

// ------------------------ k2: mark presence ---------------------------------
__global__ void k_mark(const int* __restrict__ tp){
    int i = blockIdx.x*blockDim.x + threadIdx.x;
    if(i < BB*TT){
        int v = tp[i];
        v = min(max(v, 0), TMAXV-1);
        g_pres[v] = 1;
    }
}

// ------------------------ k3: unique/rank/query/grid ------------------------
__global__ void k_build(){
    __shared__ int cnt[256];
    __shared__ int su[QPADV];
    __shared__ int sNU, sNit;
    int tid = threadIdx.x;
    int base = tid*8;
    int c = 0;
    for(int i = 0; i < 8; i++){ int v = base+i; if(v < TMAXV && g_pres[v]) c++; }
    cnt[tid] = c;
    __syncthreads();
    if(tid == 0){
        int run = 0;
        for(int i = 0; i < 256; i++){ int t = cnt[i]; cnt[i] = run; run += t; }
        sNU = run;
    }
    __syncthreads();
    int r = cnt[tid];
    for(int i = 0; i < 8; i++){
        int v = base+i;
        if(v < TMAXV){
            if(g_pres[v]){ g_rank[v] = r; su[r] = v; r++; }
            else g_rank[v] = 0;
        }
    }
    __syncthreads();
    int U = sNU;
    int mx = su[U-1];
    float t0f = (float)su[0]/SCALE_F;
    float t1f = (float)mx/SCALE_F;
    if(tid == 0){
        double nd = ceil(((double)t1f - (double)t0f)/0.05 + 1.0);
        int nit = (int)nd;
        if(nit < 2) nit = 2;
        if(nit > MAXG) nit = MAXG;
        g_niters = nit; sNit = nit;
    }
    __syncthreads();
    int nit = sNit;
    for(int q = tid; q < QPADV; q += 256){
        int v = (q < U) ? su[q] : mx;
        g_qt[q] = (float)v/SCALE_F;
    }
    double t0d = (double)t0f, t1d = (double)t1f;
    for(int i = tid; i < nit; i += 256){
        double gd = (double)i*0.05 + t0d;
        if(i == nit-1 && gd > t1d) gd = t1d;
        g_grid[i] = (float)gd;
    }
}

// ------------------------ k4: GI = x@Wih + bih ------------------------------
#define GITILE 32
__global__ __launch_bounds__(384) void k_gi(const float* __restrict__ obs,
                                            const void* __restrict__ maskp,
                                            const int* __restrict__ tp,
                                            const float* __restrict__ Wih,
                                            const float* __restrict__ bih){
    __shared__ float xs[GITILE][DIN];
    int tid = threadIdx.x;
    int mode = g_maskmode;
    int base = blockIdx.x * GITILE;
    for(int i = tid; i < GITILE*DIN; i += 384){
        int p = i / DIN, d = i - p*DIN;
        int bp = base + p;
        int t = bp & (TT-1);
        float v;
        if(d < NLL){
            float m = mread(maskp, (size_t)bp*NLL + d, mode);
            v = m * obs[(size_t)bp*NLL + d];
        } else if(d < 2*NLL){
            v = mread(maskp, (size_t)bp*NLL + (d-NLL), mode);
        } else {
            v = (t == 0) ? 0.0f : (float)(tp[bp] - tp[bp-1]);
        }
        xs[p][d] = v;
    }
    __syncthreads();
    int j = tid;
    float w[DIN];
    #pragma unroll
    for(int d = 0; d < DIN; d++) w[d] = Wih[d*G3 + j];
    float bj = bih[j];
    for(int p = 0; p < GITILE; p++){
        float acc = bj;
        #pragma unroll
        for(int d = 0; d < DIN; d++) acc = fmaf(xs[p][d], w[d], acc);
        g_GI[(size_t)(base+p)*G3 + j] = acc;
    }
}

// ------------------------ k5: GRU (sequential, 4 rows/CTA) ------------------
__global__ __launch_bounds__(384,1) void k_gru(const float* __restrict__ Whh,
                                               const float* __restrict__ bhh){
    extern __shared__ float sm[];
    float4* h4    = (float4*)sm;          // 128
    float4* gh4   = h4 + HIDD;            // 384
    float4* gi4   = gh4 + G3;             // 384
    float*  whh_s = (float*)(gi4 + G3);   // 128*384
    int j  = threadIdx.x;
    int b0 = blockIdx.x * 4;
    for(int i = j; i < HIDD*G3; i += 384) whh_s[i] = Whh[i];
    if(j < HIDD) h4[j] = make_float4(0.f,0.f,0.f,0.f);
    float bj = bhh[j];
    const size_t rs = (size_t)TT*G3;
    const float* Gp0 = g_GI + (size_t)(b0+0)*rs;
    const float* Gp1 = g_GI + (size_t)(b0+1)*rs;
    const float* Gp2 = g_GI + (size_t)(b0+2)*rs;
    const float* Gp3 = g_GI + (size_t)(b0+3)*rs;
    __syncthreads();
    for(int s = 0; s < TT; s++){
        int t = TT-1-s;
        size_t off = (size_t)t*G3 + j;
        float gi0 = Gp0[off], gi1 = Gp1[off], gi2 = Gp2[off], gi3 = Gp3[off];
        float a0 = 0.f, a1 = 0.f, a2 = 0.f, a3 = 0.f;
        #pragma unroll 8
        for(int k = 0; k < HIDD; k++){
            float4 h = h4[k];
            float  w = whh_s[k*G3 + j];
            a0 = fmaf(h.x, w, a0); a1 = fmaf(h.y, w, a1);
            a2 = fmaf(h.z, w, a2); a3 = fmaf(h.w, w, a3);
        }
        gh4[j] = make_float4(a0+bj, a1+bj, a2+bj, a3+bj);
        gi4[j] = make_float4(gi0, gi1, gi2, gi3);
        __syncthreads();
        if(j < HIDD){
            float4 ir = gi4[j], iz = gi4[j+HIDD], in = gi4[j+2*HIDD];
            float4 hr = gh4[j], hz = gh4[j+HIDD], hn = gh4[j+2*HIDD];
            float4 hv = h4[j];
            { float r = fsigm(ir.x+hr.x), z = fsigm(iz.x+hz.x);
              float n = tanhf(in.x + r*hn.x); hv.x = (1.f-z)*n + z*hv.x; }
            { float r = fsigm(ir.y+hr.y), z = fsigm(iz.y+hz.y);
              float n = tanhf(in.y + r*hn.y); hv.y = (1.f-z)*n + z*hv.y; }
            { float r = fsigm(ir.z+hr.z), z = fsigm(iz.z+hz.z);
              float n = tanhf(in.z + r*hn.z); hv.z = (1.f-z)*n + z*hv.z; }
            { float r = fsigm(ir.w+hr.w), z = fsigm(iz.w+hz.w);
              float n = tanhf(in.w + r*hn.w); hv.w = (1.f-z)*n + z*hv.w; }
            h4[j] = hv;
        }
        __syncthreads();
    }
    if(j < HIDD){
        float4 hv = h4[j];
        g_h[(b0+0)*HIDD + j] = hv.x;
        g_h[(b0+1)*HIDD + j] = hv.y;
        g_h[(b0+2)*HIDD + j] = hv.z;
        g_h[(b0+3)*HIDD + j] = hv.w;
    }
}

// ------------------------ k6: mu/logvar/z0/KL -------------------------------
__global__ __launch_bounds__(64) void k_latent(const float* __restrict__ Wmu,
                                               const float* __restrict__ bmu,
                                               const float* __restrict__ Wlv,
                                               const float* __restrict__ blv,
                                               const float* __restrict__ eps){
    __shared__ float hs[HIDD];
    __shared__ float red[LATD];
    int b = blockIdx.x, tid = threadIdx.x;
    hs[tid] = g_h[b*HIDD + tid];
    hs[tid+64] = g_h[b*HIDD + tid + 64];
    __syncthreads();
    float mu = bmu[tid], lv = blv[tid];
    #pragma unroll 8
    for(int k = 0; k < HIDD; k++){
        float h = hs[k];
        mu = fmaf(h, Wmu[k*LATD + tid], mu);
        lv = fmaf(h, Wlv[k*LATD + tid], lv);
    }
    g_z0[b*LATD + tid] = mu + eps[b*LATD + tid]*expf(0.5f*lv);
    red[tid] = 1.0f + lv - mu*mu - expf(lv);
    __syncthreads();
    if(tid == 0){
        float s = 0.f;
        for(int i = 0; i < LATD; i++) s += red[i];
        atomicAdd(&g_kl, (double)s);
    }
}

// ------------------------ k7: RK4 latent ODE --------------------------------
__global__ __launch_bounds__(128,1) void k_rk4(const float* __restrict__ W1,
                                               const float* __restrict__ b1,
                                               const float* __restrict__ W2,
                                               const float* __restrict__ b2,
                                               const float* __restrict__ W3,
                                               const float* __restrict__ b3){
    extern __shared__ float sm[];
    float4* zin4 = (float4*)sm;           // 64
    float4* a14  = zin4 + 64;             // 128
    float4* a24  = a14 + 128;             // 128
    float4* y4   = a24 + 128;             // 64
    float4* kc4  = y4 + 64;               // 64
    float*  w1s  = (float*)(kc4 + 64);    // 64*128
    float*  w2s  = w1s + 64*128;          // 128*128
    float*  w3s  = w2s + 128*128;         // 128*64
    float*  b1s  = w3s + 128*64;
    float*  b2s  = b1s + 128;
    float*  b3s  = b2s + 128;
    float*  gr   = b3s + 64;              // MAXG
    int tid = threadIdx.x;
    int j   = tid;
    int c3  = tid & 63;
    int pr  = tid >> 6;   // 0: rows 0,1   1: rows 2,3  (warp-uniform)
    for(int i = tid; i < 64*128;  i += 128) w1s[i] = W1[i];
    for(int i = tid; i < 128*128; i += 128) w2s[i] = W2[i];
    for(int i = tid; i < 128*64;  i += 128) w3s[i] = W3[i];
    b1s[tid] = b1[tid];
    b2s[tid] = b2[tid];
    if(tid < 64) b3s[tid] = b3[tid];
    int nit = g_niters;
    for(int i = tid; i < nit; i += 128) gr[i] = g_grid[i];
    int b0 = blockIdx.x * 4;
    if(tid < 64){
        float4 z;
        z.x = g_z0[(b0+0)*LATD + tid];
        z.y = g_z0[(b0+1)*LATD + tid];
        z.z = g_z0[(b0+2)*LATD + tid];
        z.w = g_z0[(b0+3)*LATD + tid];
        y4[tid] = z; zin4[tid] = z;
        g_ys[(size_t)(b0+0)*LATD + tid] = z.x;
        g_ys[(size_t)(b0+1)*LATD + tid] = z.y;
        g_ys[(size_t)(b0+2)*LATD + tid] = z.z;
        g_ys[(size_t)(b0+3)*LATD + tid] = z.w;
    }
    __syncthreads();
    const float2* a2v = (const float2*)a24;
    float2* zin2 = (float2*)zin4;
    float2* y2   = (float2*)y4;
    float2* kc2  = (float2*)kc4;
    for(int step = 0; step < nit-1; step++){
        float hs = gr[step+1] - gr[step];
        #pragma unroll
        for(int e = 0; e < 4; e++){
            // layer 1: 64 -> 128, tanh
            float ax = b1s[j], ay = ax, az = ax, aw = ax;
            #pragma unroll 8
            for(int k = 0; k < 64; k++){
                float4 z = zin4[k];
                float  w = w1s[k*128 + j];
                ax = fmaf(z.x, w, ax); ay = fmaf(z.y, w, ay);
                az = fmaf(z.z, w, az); aw = fmaf(z.w, w, aw);
            }
            a14[j] = make_float4(tanhf(ax), tanhf(ay), tanhf(az), tanhf(aw));
            __syncthreads();
            // layer 2: 128 -> 128, tanh
            float bx = b2s[j], by = bx, bz = bx, bw = bx;
            #pragma unroll 8
            for(int k = 0; k < 128; k++){
                float4 a = a14[k];
                float  w = w2s[k*128 + j];
                bx = fmaf(a.x, w, bx); by = fmaf(a.y, w, by);
                bz = fmaf(a.z, w, bz); bw = fmaf(a.w, w, bw);
            }
            a24[j] = make_float4(tanhf(bx), tanhf(by), tanhf(bz), tanhf(bw));
            __syncthreads();
            // layer 3: 128 -> 64 (no activation), 2 rows per thread
            float fx = b3s[c3], fy = fx;
            #pragma unroll 8
            for(int k = 0; k < 128; k++){
                float2 av = a2v[k*2 + pr];
                float  w  = w3s[k*64 + c3];
                fx = fmaf(av.x, w, fx); fy = fmaf(av.y, w, fy);
            }
            // RK4 combine (thread owns rows 2*pr, 2*pr+1 of lat c3)
            int idx = c3*2 + pr;
            float2 yv = y2[idx];
            if(e == 0){
                kc2[idx] = make_float2(fx, fy);
                zin2[idx] = make_float2(yv.x + 0.5f*hs*fx, yv.y + 0.5f*hs*fy);
            } else if(e == 1){
                float2 kv = kc2[idx];
                kc2[idx] = make_float2(kv.x + 2.f*fx, kv.y + 2.f*fy);
                zin2[idx] = make_float2(yv.x + 0.5f*hs*fx, yv.y + 0.5f*hs*fy);
            } else if(e == 2){
                float2 kv = kc2[idx];
                kc2[idx] = make_float2(kv.x + 2.f*fx, kv.y + 2.f*fy);
                zin2[idx] = make_float2(yv.x + hs*fx, yv.y + hs*fy);
            } else {
                float2 kv = kc2[idx];
                float h6 = hs/6.0f;
                float ynx = yv.x + h6*(kv.x + fx);
                float yny = yv.y + h6*(kv.y + fy);
                y2[idx] = make_float2(ynx, yny);
                zin2[idx] = make_float2(ynx, yny);
                g_ys[((size_t)(step+1)*BB + b0 + 2*pr  )*LATD + c3] = ynx;
                g_ys[((size_t)(step+1)*BB + b0 + 2*pr+1)*LATD + c3] = yny;
            }
            __syncthreads();
        }
    }
}

// ------------------------ interp helper -------------------------------------
__device__ __forceinline__ void interp_coeff(float qt, int nit, int* gi_out, float* w_out){
    int lo = 0, hi = nit;
    while(lo < hi){
        int mid = (lo + hi) >> 1;
        if(g_grid[mid] <= qt) lo = mid + 1; else hi = mid;
    }
    int gi = lo - 1;
    gi = max(0, min(gi, nit-2));
    float tl = g_grid[gi], tr = g_grid[gi+1];
    float den = tr - tl; if(den == 0.0f) den = 1.0f;
    *gi_out = gi;
    *w_out = (qt - tl) / den;
}

// ------------------------ k8: recon loss ------------------------------------
__global__ __launch_bounds__(128) void k_recon(const float* __restrict__ Wo1,
                                               const float* __restrict__ bo1,
                                               const float* __restrict__ Wo2,
                                               const float* __restrict__ bo2,
                                               const float* __restrict__ obs,
                                               const void* __restrict__ maskp,
                                               const int* __restrict__ tp,
                                               const int* __restrict__ seq_lens){
    extern __shared__ float sm[];
    float* wo1s = sm;                 // 64*128
    float* wo2s = wo1s + 64*128;      // 128*32
    float* bo1s = wo2s + 128*32;      // 128
    float* bo2s = bo1s + 128;         // 32
    float* zs   = bo2s + 32;          // 64*64
    float* h1s  = zs + TT*LATD;       // 128
    float* tw   = h1s + 128;          // 64
    int*   tgi  = (int*)(tw + TT);    // 64
    int tid = threadIdx.x, b = blockIdx.x;
    int mode = g_maskmode;
    for(int i = tid; i < 64*128; i += 128) wo1s[i] = Wo1[i];
    for(int i = tid; i < 128*32; i += 128) wo2s[i] = Wo2[i];
    bo1s[tid] = bo1[tid];
    if(tid < 32) bo2s[tid] = bo2[tid];
    int nit = g_niters;
    if(tid < TT){
        int v = tp[b*TT + tid];
        v = min(max(v, 0), TMAXV-1);
        float qt = g_qt[g_rank[v]];
        int gi; float w;
        interp_coeff(qt, nit, &gi, &w);
        tgi[tid] = gi; tw[tid] = w;
    }
    __syncthreads();
    for(int i = tid; i < TT*LATD; i += 128){
        int t = i >> 6, l = i & 63;
        int gi = tgi[t]; float w = tw[t];
        float zl = g_ys[((size_t)gi*BB + b)*LATD + l];
        float zr = g_ys[((size_t)(gi+1)*BB + b)*LATD + l];
        zs[i] = zl*(1.0f - w) + zr*w;
    }
    __syncthreads();
    int sl = seq_lens[b];
    if(sl > TT) sl = TT;
    double lsse = 0.0; float lnm = 0.0f;
    for(int t = 0; t < sl; t++){
        float acc = bo1s[tid];
        #pragma unroll 8
        for(int k = 0; k < 64; k++) acc = fmaf(zs[t*64+k], wo1s[k*128 + tid], acc);
        h1s[tid] = fmaxf(acc, 0.0f);
        __syncthreads();
        if(tid < NLL){
            float o = bo2s[tid];
            #pragma unroll 8
            for(int k = 0; k < 128; k++) o = fmaf(h1s[k], wo2s[k*32 + tid], o);
            float m = mread(maskp, (size_t)(b*TT + t)*NLL + tid, mode);
            float d = o - obs[(size_t)(b*TT + t)*NLL + tid];
            lsse += (double)(m*d*d);
            lnm  += m;
        }
        __syncthreads();
    }
    if(tid < 32){
        #pragma unroll
        for(int o = 16; o > 0; o >>= 1){
            lsse += __shfl_down_sync(0xffffffffu, lsse, o);
            lnm  += __shfl_down_sync(0xffffffffu, lnm,  o);
        }
        if(tid == 0){
            atomicAdd(&g_sse, lsse);
            atomicAdd(&g_nobs, (double)lnm);
        }
    }
}

// ------------------------ k9: z_eval + hazard -------------------------------
__global__ __launch_bounds__(128) void k_hazard(const float* __restrict__ Ws1,
                                                const float* __restrict__ bs1,
                                                const float* __restrict__ Ws2,
                                                const float* __restrict__ bs2,
                                                const float* __restrict__ age,
                                                const int* __restrict__ tp,
                                                const int* __restrict__ seq_lens,
                                                float* __restrict__ out){
    __shared__ float zev[DIN];    // z_eval (64) + age (1)
    __shared__ float hbuf[HIDD];
    int tid = threadIdx.x, b = blockIdx.x;
    int nit = g_niters;
    int sl = seq_lens[b];
    if(sl < 1) sl = 1; if(sl > TT) sl = TT;
    int v = tp[b*TT + sl - 1];
    v = min(max(v, 0), TMAXV-1);
    float qt = g_qt[g_rank[v]];
    int gi; float w;
    interp_coeff(qt, nit, &gi, &w);
    if(tid < LATD){
        float zl = g_ys[((size_t)gi*BB + b)*LATD + tid];
        float zr = g_ys[((size_t)(gi+1)*BB + b)*LATD + tid];
        float z = zl*(1.0f - w) + zr*w;
        zev[tid] = z;
        out[1026 + b*LATD + tid] = z;   // z_eval output
    }
    if(tid == 0) zev[LATD] = age[b];
    __syncthreads();
    float acc = bs1[tid];
    #pragma unroll 8
    for(int k = 0; k < DIN; k++) acc = fmaf(zev[k], Ws1[k*HIDD + tid], acc);
    hbuf[tid] = fmaxf(acc, 0.0f);
    __syncthreads();
    if(tid < 2){
        float o = bs2[tid];
        #pragma unroll 8
        for(int k = 0; k < HIDD; k++) o = fmaf(hbuf[k], Ws2[k*2 + tid], o);
        out[b*2 + tid] = o;             // log_hazard output
    }
}

// ------------------------ k10: write scalars --------------------------------
__global__ void k_final(float* __restrict__ out){
    if(threadIdx.x == 0){
        double n = g_nobs;
        out[1024] = (n > 0.0) ? (float)(g_sse / fmax(n, 1.0)) : 0.0f;   // recon
        out[1025] = (float)(-0.5 * g_kl / (double)BB);                   // kl
    }
}

// ------------------------ launch --------------------------------------------
extern "C" void kernel_launch(void* const* d_in, const int* in_sizes, int n_in,
                              void* d_out, int out_size){
    (void)in_sizes; (void)n_in; (void)out_size;
    const float* obs = (const float*)d_in[0];
    const float* age = (const float*)d_in[1];
    const float* eps = (const float*)d_in[2];
    const float* Wih = (const float*)d_in[3];
    const float* Whh = (const float*)d_in[4];
    const float* bih = (const float*)d_in[5];
    const float* bhh = (const float*)d_in[6];
    const float* Wmu = (const float*)d_in[7];
    const float* bmu = (const float*)d_in[8];
    const float* Wlv = (const float*)d_in[9];
    const float* blv = (const float*)d_in[10];
    const float* W1  = (const float*)d_in[11];
    const float* b1  = (const float*)d_in[12];
    const float* W2  = (const float*)d_in[13];
    const float* b2  = (const float*)d_in[14];
    const float* W3  = (const float*)d_in[15];
    const float* b3  = (const float*)d_in[16];
    const float* Wo1 = (const float*)d_in[17];
    const float* bo1 = (const float*)d_in[18];
    const float* Wo2 = (const float*)d_in[19];
    const float* bo2 = (const float*)d_in[20];
    const float* Ws1 = (const float*)d_in[21];
    const float* bs1 = (const float*)d_in[22];
    const float* Ws2 = (const float*)d_in[23];
    const float* bs2 = (const float*)d_in[24];
    const void*  msk = d_in[25];
    const int*   tp  = (const int*)d_in[26];
    const int*   seq = (const int*)d_in[27];
    float* out = (float*)d_out;

    const int GRU_SMEM = (HIDD + 2*G3)*16 + HIDD*G3*4;            // 210944
    const int RK4_SMEM = 448*16 + (64*128 + 128*128 + 128*64)*4
                         + (128+128+64+MAXG)*4;                    // ~140192
    const int REC_SMEM = (64*128 + 128*32 + 128 + 32 + TT*LATD + 128 + TT)*4
                         + TT*4;                                   // ~67328

    cudaFuncSetAttribute(k_gru,   cudaFuncAttributeMaxDynamicSharedMemorySize, GRU_SMEM);
    cudaFuncSetAttribute(k_rk4,   cudaFuncAttributeMaxDynamicSharedMemorySize, RK4_SMEM);
    cudaFuncSetAttribute(k_recon, cudaFuncAttributeMaxDynamicSharedMemorySize, REC_SMEM);

    k_zero  <<<9, 256>>>();
    k_detect<<<1, 256>>>(msk);
    k_mark  <<<(BB*TT + 255)/256, 256>>>(tp);
    k_build <<<1, 256>>>();
    k_gi    <<<BB*TT/GITILE, 384>>>(obs, msk, tp, Wih, bih);
    k_gru   <<<BB/4, 384, GRU_SMEM>>>(Whh, bhh);
    k_latent<<<BB, 64>>>(Wmu, bmu, Wlv, blv, eps);
    k_rk4   <<<BB/4, 128, RK4_SMEM>>>(W1, b1, W2, b2, W3, b3);
    k_recon <<<BB, 128, REC_SMEM>>>(Wo1, bo1, Wo2, bo2, obs, msk, tp, seq);
    k_hazard<<<BB, 128>>>(Ws1, bs1, Ws2, bs2, age, tp, seq, out);
    k_final <<<1, 32>>>(out);
}